// round 1
// baseline (speedup 1.0000x reference)
#include <cuda_runtime.h>
#include <math.h>

#define D_MODEL 1024
#define N_HEADS 16
#define D_K     64
#define BATCH   4
#define SEQ     2048
#define M_TOTAL (BATCH * SEQ)   // 8192

// ---------------- scratch (device globals: allocation-free) ----------------
__device__ float g_qh[BATCH * N_HEADS * SEQ * D_K];   // [B,H,L,Dk]
__device__ float g_kh[BATCH * N_HEADS * SEQ * D_K];
__device__ float g_vh[BATCH * N_HEADS * SEQ * D_K];
__device__ float g_att[M_TOTAL * D_MODEL];            // [B,L,D]

// ---------------- 128x128x16 register-blocked SGEMM ----------------
// C[m][n] = sum_k A[m][k] * W[n][k] + bias[n]
// HEAD=true: scatter C into [B,H,L,Dk] head layout; else row-major [M,D].
template <bool HEAD>
__device__ __forceinline__ void gemm_body(const float* __restrict__ A,
                                          const float* __restrict__ W,
                                          const float* __restrict__ bias,
                                          float* __restrict__ C)
{
    __shared__ __align__(16) float As[16][132];   // k-major, padded
    __shared__ __align__(16) float Ws[16][132];

    const int tid = threadIdx.x;
    const int tx = tid & 15;          // 0..15 -> n micro-tile
    const int ty = tid >> 4;          // 0..15 -> m micro-tile
    const int m0 = blockIdx.y * 128;
    const int n0 = blockIdx.x * 128;

    float acc[8][8];
#pragma unroll
    for (int i = 0; i < 8; i++)
#pragma unroll
        for (int j = 0; j < 8; j++) acc[i][j] = 0.f;

    for (int k0 = 0; k0 < D_MODEL; k0 += 16) {
        __syncthreads();
#pragma unroll
        for (int p = 0; p < 2; p++) {
            int q  = tid + p * 256;       // 0..511 quads
            int r  = q >> 2;              // row in tile 0..127
            int qi = q & 3;               // quad within 16-wide k slab
            float4 fa = *(const float4*)(A + (size_t)(m0 + r) * D_MODEL + k0 + qi * 4);
            float4 fw = *(const float4*)(W + (size_t)(n0 + r) * D_MODEL + k0 + qi * 4);
            As[qi * 4 + 0][r] = fa.x; As[qi * 4 + 1][r] = fa.y;
            As[qi * 4 + 2][r] = fa.z; As[qi * 4 + 3][r] = fa.w;
            Ws[qi * 4 + 0][r] = fw.x; Ws[qi * 4 + 1][r] = fw.y;
            Ws[qi * 4 + 2][r] = fw.z; Ws[qi * 4 + 3][r] = fw.w;
        }
        __syncthreads();
#pragma unroll
        for (int k = 0; k < 16; k++) {
            float a[8], b[8];
            *(float4*)&a[0] = *(const float4*)&As[k][ty * 8];
            *(float4*)&a[4] = *(const float4*)&As[k][ty * 8 + 4];
            *(float4*)&b[0] = *(const float4*)&Ws[k][tx * 8];
            *(float4*)&b[4] = *(const float4*)&Ws[k][tx * 8 + 4];
#pragma unroll
            for (int i = 0; i < 8; i++)
#pragma unroll
                for (int j = 0; j < 8; j++)
                    acc[i][j] += a[i] * b[j];
        }
    }

#pragma unroll
    for (int i = 0; i < 8; i++) {
        const int m = m0 + ty * 8 + i;
#pragma unroll
        for (int j = 0; j < 8; j++) {
            const int n = n0 + tx * 8 + j;
            const float v = acc[i][j] + bias[n];
            if (HEAD) {
                const int bb = m >> 11;           // m / SEQ
                const int l  = m & (SEQ - 1);
                const int h  = n >> 6;            // n / D_K
                const int dk = n & (D_K - 1);
                C[((size_t)(bb * N_HEADS + h) * SEQ + l) * D_K + dk] = v;
            } else {
                C[(size_t)m * D_MODEL + n] = v;
            }
        }
    }
}

__global__ void __launch_bounds__(256) proj_kernel(
    const float* __restrict__ Q,  const float* __restrict__ K,  const float* __restrict__ V,
    const float* __restrict__ Wq, const float* __restrict__ Wk, const float* __restrict__ Wv,
    const float* __restrict__ bq, const float* __restrict__ bk, const float* __restrict__ bv)
{
    const int z = blockIdx.z;
    if (z == 0)      gemm_body<true>(Q, Wq, bq, g_qh);
    else if (z == 1) gemm_body<true>(K, Wk, bk, g_kh);
    else             gemm_body<true>(V, Wv, bv, g_vh);
}

__global__ void __launch_bounds__(256) out_kernel(
    const float* __restrict__ Wo, const float* __restrict__ bo, float* __restrict__ out)
{
    gemm_body<false>(g_att, Wo, bo, out);
}

// ---------------- flash-style causal attention ----------------
// Block: 64 q-rows of one (b,h). 64x64 KV tiles, online softmax.
#define SLD 65   // smem leading dim (pad to kill bank conflicts)

__global__ void __launch_bounds__(256) attn_kernel()
{
    extern __shared__ float sm[];
    float* Qs   = sm;                  // [64][SLD]
    float* Ks   = sm + 64 * SLD;
    float* Vs   = sm + 2 * 64 * SLD;
    float* Ss   = sm + 3 * 64 * SLD;
    float* m_s  = sm + 4 * 64 * SLD;   // [64]
    float* l_s  = m_s + 64;            // [64]
    float* cf_s = l_s + 64;            // [64]

    const int tid  = threadIdx.x;
    const int tx   = tid & 15;
    const int ty   = tid >> 4;
    const int row0 = ty * 4;
    const int col0 = tx * 4;
    const int bh   = blockIdx.y;                            // b*16 + h
    const int q0   = (gridDim.x - 1 - blockIdx.x) * 64;     // heavy blocks first

    // load Q tile once
    const float* qb = g_qh + ((size_t)bh * SEQ + q0) * D_K;
#pragma unroll
    for (int i = 0; i < 16; i++) {
        int idx = tid + i * 256;
        int r = idx >> 6, c = idx & 63;
        Qs[r * SLD + c] = qb[r * 64 + c];
    }
    if (tid < 64) { m_s[tid] = -1e30f; l_s[tid] = 0.f; }

    float o[4][4];
#pragma unroll
    for (int i = 0; i < 4; i++)
#pragma unroll
        for (int j = 0; j < 4; j++) o[i][j] = 0.f;

    for (int t0 = 0; t0 <= q0; t0 += 64) {
        __syncthreads();   // previous iteration done with Ks/Vs/Ss
        const float* kb = g_kh + ((size_t)bh * SEQ + t0) * D_K;
        const float* vb = g_vh + ((size_t)bh * SEQ + t0) * D_K;
#pragma unroll
        for (int i = 0; i < 16; i++) {
            int idx = tid + i * 256;
            int r = idx >> 6, c = idx & 63;
            Ks[r * SLD + c] = kb[r * 64 + c];
            Vs[r * SLD + c] = vb[r * 64 + c];
        }
        __syncthreads();

        // S = Q K^T (4x4 per thread)
        float s[4][4];
#pragma unroll
        for (int i = 0; i < 4; i++)
#pragma unroll
            for (int j = 0; j < 4; j++) s[i][j] = 0.f;

#pragma unroll 8
        for (int k = 0; k < 64; k++) {
            float qv[4], kv[4];
#pragma unroll
            for (int i = 0; i < 4; i++) qv[i] = Qs[(row0 + i) * SLD + k];
#pragma unroll
            for (int j = 0; j < 4; j++) kv[j] = Ks[(col0 + j) * SLD + k];
#pragma unroll
            for (int i = 0; i < 4; i++)
#pragma unroll
                for (int j = 0; j < 4; j++)
                    s[i][j] += qv[i] * kv[j];
        }

        const bool diag = (t0 == q0);
#pragma unroll
        for (int i = 0; i < 4; i++)
#pragma unroll
            for (int j = 0; j < 4; j++) {
                float v = s[i][j] * 0.125f;   // 1/sqrt(64)
                if (diag && (col0 + j > row0 + i)) v = -1e30f;
                Ss[(row0 + i) * SLD + col0 + j] = v;
            }
        __syncthreads();

        // online softmax row pass (64 threads, one row each)
        if (tid < 64) {
            float* srow = Ss + tid * SLD;
            const float mo = m_s[tid];
            float mx = mo;
#pragma unroll 8
            for (int c = 0; c < 64; c++) mx = fmaxf(mx, srow[c]);
            const float cf = __expf(mo - mx);
            float sum = 0.f;
#pragma unroll 8
            for (int c = 0; c < 64; c++) {
                float p = __expf(srow[c] - mx);
                srow[c] = p;
                sum += p;
            }
            l_s[tid]  = l_s[tid] * cf + sum;
            m_s[tid]  = mx;
            cf_s[tid] = cf;
        }
        __syncthreads();

        // O = O*cf + P @ V
        float cfr[4];
#pragma unroll
        for (int i = 0; i < 4; i++) {
            cfr[i] = cf_s[row0 + i];
#pragma unroll
            for (int j = 0; j < 4; j++) o[i][j] *= cfr[i];
        }
#pragma unroll 8
        for (int c = 0; c < 64; c++) {
            float pv[4], vv[4];
#pragma unroll
            for (int i = 0; i < 4; i++) pv[i] = Ss[(row0 + i) * SLD + c];
#pragma unroll
            for (int j = 0; j < 4; j++) vv[j] = Vs[c * SLD + col0 + j];
#pragma unroll
            for (int i = 0; i < 4; i++)
#pragma unroll
                for (int j = 0; j < 4; j++)
                    o[i][j] += pv[i] * vv[j];
        }
    }

    // epilogue: normalize and write [B,L,D] (ready for output projection)
    const int bb = bh >> 4;
    const int h  = bh & 15;
#pragma unroll
    for (int i = 0; i < 4; i++) {
        const float inv = 1.f / l_s[row0 + i];
#pragma unroll
        for (int j = 0; j < 4; j++) {
            g_att[((size_t)bb * SEQ + (q0 + row0 + i)) * D_MODEL + h * D_K + col0 + j] =
                o[i][j] * inv;
        }
    }
}

// ---------------- launch ----------------
extern "C" void kernel_launch(void* const* d_in, const int* in_sizes, int n_in,
                              void* d_out, int out_size)
{
    const float* Q = (const float*)d_in[0];
    const float* K = (const float*)d_in[1];
    const float* V = (const float*)d_in[2];
    // mask (L*L int32) may sit at slot 3 (dict order) or at the end (arg order).
    const int wb = (n_in > 3 && in_sizes[3] == SEQ * SEQ) ? 4 : 3;
    const float* Wq = (const float*)d_in[wb + 0];
    const float* bq = (const float*)d_in[wb + 1];
    const float* Wk = (const float*)d_in[wb + 2];
    const float* bk = (const float*)d_in[wb + 3];
    const float* Wv = (const float*)d_in[wb + 4];
    const float* bv = (const float*)d_in[wb + 5];
    const float* Wo = (const float*)d_in[wb + 6];
    const float* bo = (const float*)d_in[wb + 7];
    float* out = (float*)d_out;

    const int attn_smem = (4 * 64 * SLD + 192) * (int)sizeof(float);  // 67328 B
    cudaFuncSetAttribute(attn_kernel, cudaFuncAttributeMaxDynamicSharedMemorySize, attn_smem);

    dim3 blk(256);
    proj_kernel<<<dim3(D_MODEL / 128, M_TOTAL / 128, 3), blk>>>(Q, K, V, Wq, Wk, Wv, bq, bk, bv);
    attn_kernel<<<dim3(SEQ / 64, BATCH * N_HEADS), blk, attn_smem>>>();
    out_kernel<<<dim3(D_MODEL / 128, M_TOTAL / 128), blk>>>(Wo, bo, out);
}

// round 4
// speedup vs baseline: 1.6860x; 1.6860x over previous
#include <cuda_runtime.h>
#include <math.h>
#include <stdint.h>

#define D_MODEL 1024
#define N_HEADS 16
#define D_K     64
#define BATCH   4
#define SEQ     2048
#define M_TOTAL (BATCH * SEQ)   // 8192

// GEMM tiling
#define BK      16
#define NCHUNK  (D_MODEL / BK)        // 64
#define RSTRIDE 20                    // padded row stride in words (conflict-free frags)
#define TILE_WORDS (128 * RSTRIDE)    // per matrix per stage
#define DSMEM_BYTES (2 * 2 * TILE_WORDS * 4)   // 2 stages x (A,B) = 40960 B

// ---------------- scratch (device globals: allocation-free) ----------------
__device__ float g_qh[BATCH * N_HEADS * SEQ * D_K];   // [B,H,L,Dk]
__device__ float g_kh[BATCH * N_HEADS * SEQ * D_K];
__device__ float g_vh[BATCH * N_HEADS * SEQ * D_K];
__device__ float g_att[M_TOTAL * D_MODEL];            // [B,L,D]

// ---------------- helpers ----------------
__device__ __forceinline__ uint32_t f2tf32(float x) {
    uint32_t r; asm("cvt.rna.tf32.f32 %0, %1;" : "=r"(r) : "f"(x)); return r;
}
__device__ __forceinline__ void mma_tf32_16x8x8(float* c, const uint32_t* a, const uint32_t* b) {
    asm volatile(
        "mma.sync.aligned.m16n8k8.row.col.f32.tf32.tf32.f32 "
        "{%0,%1,%2,%3}, {%4,%5,%6,%7}, {%8,%9}, {%0,%1,%2,%3};"
        : "+f"(c[0]), "+f"(c[1]), "+f"(c[2]), "+f"(c[3])
        : "r"(a[0]), "r"(a[1]), "r"(a[2]), "r"(a[3]), "r"(b[0]), "r"(b[1]));
}

// ---------------- tf32 tensor-core GEMM: C[m][n] = sum_k A[m][k]*W[n][k] + bias[n] ----------------
// Block 128x128, 256 threads (8 warps as 2m x 4n), warp tile 64x32, m16n8k8 fragments.
template <bool HEAD>
__device__ __forceinline__ void tc_gemm(const float* __restrict__ A,
                                        const float* __restrict__ W,
                                        const float* __restrict__ bias,
                                        float* __restrict__ C)
{
    extern __shared__ uint32_t dsm[];

    const int tid = threadIdx.x;
    const int wid = tid >> 5;
    const int lid = tid & 31;
    const int g   = lid >> 2;          // group 0..7
    const int tig = lid & 3;           // thread-in-group 0..3
    const int warp_m = wid >> 2;       // 0..1
    const int warp_n = wid & 3;        // 0..3
    const int m0 = blockIdx.y * 128;
    const int n0 = blockIdx.x * 128;

    // loader mapping: slot = tid + it*256; row = slot>>2, quad = slot&3
    const int lr = tid >> 2;           // rows this thread covers: lr, lr+64
    const int lc = tid & 3;            // float4 index within 16-col chunk

    float acc[4][4][4];
#pragma unroll
    for (int mi = 0; mi < 4; mi++)
#pragma unroll
        for (int ni = 0; ni < 4; ni++)
#pragma unroll
            for (int r = 0; r < 4; r++) acc[mi][ni][r] = 0.f;

    float4 pa[2], pb[2];

    // prologue: chunk 0
#pragma unroll
    for (int it = 0; it < 2; it++) {
        const int r = lr + it * 64;
        pa[it] = *(const float4*)(A + (size_t)(m0 + r) * D_MODEL + lc * 4);
        pb[it] = *(const float4*)(W + (size_t)(n0 + r) * D_MODEL + lc * 4);
    }
    {
        uint32_t* as = dsm;                 // stage 0 A
        uint32_t* bs = dsm + TILE_WORDS;    // stage 0 B
#pragma unroll
        for (int it = 0; it < 2; it++) {
            const int r = lr + it * 64;
            uint4 ua, ub;
            ua.x = f2tf32(pa[it].x); ua.y = f2tf32(pa[it].y); ua.z = f2tf32(pa[it].z); ua.w = f2tf32(pa[it].w);
            ub.x = f2tf32(pb[it].x); ub.y = f2tf32(pb[it].y); ub.z = f2tf32(pb[it].z); ub.w = f2tf32(pb[it].w);
            *(uint4*)(as + r * RSTRIDE + lc * 4) = ua;
            *(uint4*)(bs + r * RSTRIDE + lc * 4) = ub;
        }
    }
    __syncthreads();

    int cur = 0;
    for (int c = 0; c < NCHUNK; c++) {
        // prefetch next chunk (LDG issued early, held in regs)
        if (c + 1 < NCHUNK) {
            const int k0 = (c + 1) * BK;
#pragma unroll
            for (int it = 0; it < 2; it++) {
                const int r = lr + it * 64;
                pa[it] = *(const float4*)(A + (size_t)(m0 + r) * D_MODEL + k0 + lc * 4);
                pb[it] = *(const float4*)(W + (size_t)(n0 + r) * D_MODEL + k0 + lc * 4);
            }
        }

        // compute on current stage
        const uint32_t* as = dsm + cur * 2 * TILE_WORDS;
        const uint32_t* bs = as + TILE_WORDS;
#pragma unroll
        for (int ks = 0; ks < 2; ks++) {
            uint32_t af[4][4], bf[4][2];
#pragma unroll
            for (int mi = 0; mi < 4; mi++) {
                const uint32_t* p = as + (warp_m * 64 + mi * 16 + g) * RSTRIDE + ks * 8 + tig;
                af[mi][0] = p[0];
                af[mi][1] = p[8 * RSTRIDE];
                af[mi][2] = p[4];
                af[mi][3] = p[8 * RSTRIDE + 4];
            }
#pragma unroll
            for (int ni = 0; ni < 4; ni++) {
                const uint32_t* p = bs + (warp_n * 32 + ni * 8 + g) * RSTRIDE + ks * 8 + tig;
                bf[ni][0] = p[0];
                bf[ni][1] = p[4];
            }
#pragma unroll
            for (int mi = 0; mi < 4; mi++)
#pragma unroll
                for (int ni = 0; ni < 4; ni++)
                    mma_tf32_16x8x8(acc[mi][ni], af[mi], bf[ni]);
        }

        // store prefetched chunk into the other stage
        if (c + 1 < NCHUNK) {
            uint32_t* nas = dsm + (cur ^ 1) * 2 * TILE_WORDS;
            uint32_t* nbs = nas + TILE_WORDS;
#pragma unroll
            for (int it = 0; it < 2; it++) {
                const int r = lr + it * 64;
                uint4 ua, ub;
                ua.x = f2tf32(pa[it].x); ua.y = f2tf32(pa[it].y); ua.z = f2tf32(pa[it].z); ua.w = f2tf32(pa[it].w);
                ub.x = f2tf32(pb[it].x); ub.y = f2tf32(pb[it].y); ub.z = f2tf32(pb[it].z); ub.w = f2tf32(pb[it].w);
                *(uint4*)(nas + r * RSTRIDE + lc * 4) = ua;
                *(uint4*)(nbs + r * RSTRIDE + lc * 4) = ub;
            }
        }
        __syncthreads();
        cur ^= 1;
    }

    // epilogue: C fragment (g, 2tig) / (g, 2tig+1) / (g+8, 2tig) / (g+8, 2tig+1)
#pragma unroll
    for (int mi = 0; mi < 4; mi++) {
#pragma unroll
        for (int rr = 0; rr < 2; rr++) {
            const int m = m0 + warp_m * 64 + mi * 16 + g + rr * 8;
            const int bb = m >> 11;               // m / SEQ
            const int l  = m & (SEQ - 1);
#pragma unroll
            for (int ni = 0; ni < 4; ni++) {
#pragma unroll
                for (int cc = 0; cc < 2; cc++) {
                    const int n = n0 + warp_n * 32 + ni * 8 + 2 * tig + cc;
                    const float v = acc[mi][ni][rr * 2 + cc] + bias[n];
                    if (HEAD) {
                        const int h  = n >> 6;
                        const int dk = n & (D_K - 1);
                        C[((size_t)(bb * N_HEADS + h) * SEQ + l) * D_K + dk] = v;
                    } else {
                        C[(size_t)m * D_MODEL + n] = v;
                    }
                }
            }
        }
    }
}

__global__ void __launch_bounds__(256, 2) proj_kernel(
    const float* __restrict__ Q,  const float* __restrict__ K,  const float* __restrict__ V,
    const float* __restrict__ Wq, const float* __restrict__ Wk, const float* __restrict__ Wv,
    const float* __restrict__ bq, const float* __restrict__ bk, const float* __restrict__ bv)
{
    const int z = blockIdx.z;
    if (z == 0)      tc_gemm<true>(Q, Wq, bq, g_qh);
    else if (z == 1) tc_gemm<true>(K, Wk, bk, g_kh);
    else             tc_gemm<true>(V, Wv, bv, g_vh);
}

__global__ void __launch_bounds__(256, 2) out_kernel(
    const float* __restrict__ Wo, const float* __restrict__ bo, float* __restrict__ out)
{
    tc_gemm<false>(g_att, Wo, bo, out);
}

// ---------------- flash-style causal attention (unchanged, known-correct) ----------------
#define SLD 65

__global__ void __launch_bounds__(256) attn_kernel()
{
    extern __shared__ float sm[];
    float* Qs   = sm;
    float* Ks   = sm + 64 * SLD;
    float* Vs   = sm + 2 * 64 * SLD;
    float* Ss   = sm + 3 * 64 * SLD;
    float* m_s  = sm + 4 * 64 * SLD;
    float* l_s  = m_s + 64;
    float* cf_s = l_s + 64;

    const int tid  = threadIdx.x;
    const int tx   = tid & 15;
    const int ty   = tid >> 4;
    const int row0 = ty * 4;
    const int col0 = tx * 4;
    const int bh   = blockIdx.y;
    const int q0   = (gridDim.x - 1 - blockIdx.x) * 64;

    const float* qb = g_qh + ((size_t)bh * SEQ + q0) * D_K;
#pragma unroll
    for (int i = 0; i < 16; i++) {
        int idx = tid + i * 256;
        int r = idx >> 6, c = idx & 63;
        Qs[r * SLD + c] = qb[r * 64 + c];
    }
    if (tid < 64) { m_s[tid] = -1e30f; l_s[tid] = 0.f; }

    float o[4][4];
#pragma unroll
    for (int i = 0; i < 4; i++)
#pragma unroll
        for (int j = 0; j < 4; j++) o[i][j] = 0.f;

    for (int t0 = 0; t0 <= q0; t0 += 64) {
        __syncthreads();
        const float* kb = g_kh + ((size_t)bh * SEQ + t0) * D_K;
        const float* vb = g_vh + ((size_t)bh * SEQ + t0) * D_K;
#pragma unroll
        for (int i = 0; i < 16; i++) {
            int idx = tid + i * 256;
            int r = idx >> 6, c = idx & 63;
            Ks[r * SLD + c] = kb[r * 64 + c];
            Vs[r * SLD + c] = vb[r * 64 + c];
        }
        __syncthreads();

        float sacc[4][4];
#pragma unroll
        for (int i = 0; i < 4; i++)
#pragma unroll
            for (int j = 0; j < 4; j++) sacc[i][j] = 0.f;

#pragma unroll 8
        for (int k = 0; k < 64; k++) {
            float qv[4], kv[4];
#pragma unroll
            for (int i = 0; i < 4; i++) qv[i] = Qs[(row0 + i) * SLD + k];
#pragma unroll
            for (int j = 0; j < 4; j++) kv[j] = Ks[(col0 + j) * SLD + k];
#pragma unroll
            for (int i = 0; i < 4; i++)
#pragma unroll
                for (int j = 0; j < 4; j++)
                    sacc[i][j] += qv[i] * kv[j];
        }

        const bool diag = (t0 == q0);
#pragma unroll
        for (int i = 0; i < 4; i++)
#pragma unroll
            for (int j = 0; j < 4; j++) {
                float v = sacc[i][j] * 0.125f;
                if (diag && (col0 + j > row0 + i)) v = -1e30f;
                Ss[(row0 + i) * SLD + col0 + j] = v;
            }
        __syncthreads();

        if (tid < 64) {
            float* srow = Ss + tid * SLD;
            const float mo = m_s[tid];
            float mx = mo;
#pragma unroll 8
            for (int c = 0; c < 64; c++) mx = fmaxf(mx, srow[c]);
            const float cf = __expf(mo - mx);
            float sum = 0.f;
#pragma unroll 8
            for (int c = 0; c < 64; c++) {
                float p = __expf(srow[c] - mx);
                srow[c] = p;
                sum += p;
            }
            l_s[tid]  = l_s[tid] * cf + sum;
            m_s[tid]  = mx;
            cf_s[tid] = cf;
        }
        __syncthreads();

        float cfr[4];
#pragma unroll
        for (int i = 0; i < 4; i++) {
            cfr[i] = cf_s[row0 + i];
#pragma unroll
            for (int j = 0; j < 4; j++) o[i][j] *= cfr[i];
        }
#pragma unroll 8
        for (int c = 0; c < 64; c++) {
            float pv[4], vv[4];
#pragma unroll
            for (int i = 0; i < 4; i++) pv[i] = Ss[(row0 + i) * SLD + c];
#pragma unroll
            for (int j = 0; j < 4; j++) vv[j] = Vs[c * SLD + col0 + j];
#pragma unroll
            for (int i = 0; i < 4; i++)
#pragma unroll
                for (int j = 0; j < 4; j++)
                    o[i][j] += pv[i] * vv[j];
        }
    }

    const int bb = bh >> 4;
    const int h  = bh & 15;
#pragma unroll
    for (int i = 0; i < 4; i++) {
        const float inv = 1.f / l_s[row0 + i];
#pragma unroll
        for (int j = 0; j < 4; j++) {
            g_att[((size_t)bb * SEQ + (q0 + row0 + i)) * D_MODEL + h * D_K + col0 + j] =
                o[i][j] * inv;
        }
    }
}

// ---------------- launch ----------------
extern "C" void kernel_launch(void* const* d_in, const int* in_sizes, int n_in,
                              void* d_out, int out_size)
{
    const float* Q = (const float*)d_in[0];
    const float* K = (const float*)d_in[1];
    const float* V = (const float*)d_in[2];
    const int wb = (n_in > 3 && in_sizes[3] == SEQ * SEQ) ? 4 : 3;
    const float* Wq = (const float*)d_in[wb + 0];
    const float* bq = (const float*)d_in[wb + 1];
    const float* Wk = (const float*)d_in[wb + 2];
    const float* bk = (const float*)d_in[wb + 3];
    const float* Wv = (const float*)d_in[wb + 4];
    const float* bv = (const float*)d_in[wb + 5];
    const float* Wo = (const float*)d_in[wb + 6];
    const float* bo = (const float*)d_in[wb + 7];
    float* out = (float*)d_out;

    const int attn_smem = (4 * 64 * SLD + 192) * (int)sizeof(float);  // 67328 B
    cudaFuncSetAttribute(proj_kernel, cudaFuncAttributeMaxDynamicSharedMemorySize, DSMEM_BYTES);
    cudaFuncSetAttribute(out_kernel,  cudaFuncAttributeMaxDynamicSharedMemorySize, DSMEM_BYTES);
    cudaFuncSetAttribute(attn_kernel, cudaFuncAttributeMaxDynamicSharedMemorySize, attn_smem);

    dim3 blk(256);
    proj_kernel<<<dim3(D_MODEL / 128, M_TOTAL / 128, 3), blk, DSMEM_BYTES>>>(
        Q, K, V, Wq, Wk, Wv, bq, bk, bv);
    attn_kernel<<<dim3(SEQ / 64, BATCH * N_HEADS), blk, attn_smem>>>();
    out_kernel<<<dim3(D_MODEL / 128, M_TOTAL / 128), blk, DSMEM_BYTES>>>(Wo, bo, out);
}

// round 5
// speedup vs baseline: 2.8362x; 1.6822x over previous
#include <cuda_runtime.h>
#include <math.h>
#include <stdint.h>

#define D_MODEL 1024
#define N_HEADS 16
#define D_K     64
#define BATCH   4
#define SEQ     2048
#define M_TOTAL (BATCH * SEQ)   // 8192

// GEMM tiling
#define BK      16
#define NCHUNK  (D_MODEL / BK)        // 64
#define RSTRIDE 20                    // padded row stride in words (conflict-free frags)
#define TILE_WORDS (128 * RSTRIDE)    // per matrix per stage
#define DSMEM_BYTES (2 * 2 * TILE_WORDS * 4)   // 2 stages x (A,B) = 40960 B

// attention tiling
#define AST 68     // Q/K row stride words (64 + 4): frag banks (4g+tig) mod 32 distinct
#define PST 132    // P/Vt row stride words (128 + 4)
#define A_QS 0
#define A_KS (128 * AST)               // 8704
#define A_VT (A_KS + 128 * AST)        // 17408
#define A_PS (A_VT + 64 * PST)         // 25856
#define A_MS (A_PS + 128 * PST)        // 42752
#define A_LS (A_MS + 128)
#define A_CF (A_LS + 128)
#define ATTN_WORDS (A_CF + 128)        // 43136
#define ATTN_SMEM_BYTES (ATTN_WORDS * 4)  // 172544

// ---------------- scratch (device globals: allocation-free) ----------------
__device__ float g_qh[BATCH * N_HEADS * SEQ * D_K];   // [B,H,L,Dk]
__device__ float g_kh[BATCH * N_HEADS * SEQ * D_K];
__device__ float g_vh[BATCH * N_HEADS * SEQ * D_K];
__device__ float g_att[M_TOTAL * D_MODEL];            // [B,L,D]

// ---------------- helpers ----------------
__device__ __forceinline__ uint32_t f2tf32(float x) {
    uint32_t r; asm("cvt.rna.tf32.f32 %0, %1;" : "=r"(r) : "f"(x)); return r;
}
__device__ __forceinline__ void mma_tf32_16x8x8(float* c, const uint32_t* a, const uint32_t* b) {
    asm volatile(
        "mma.sync.aligned.m16n8k8.row.col.f32.tf32.tf32.f32 "
        "{%0,%1,%2,%3}, {%4,%5,%6,%7}, {%8,%9}, {%0,%1,%2,%3};"
        : "+f"(c[0]), "+f"(c[1]), "+f"(c[2]), "+f"(c[3])
        : "r"(a[0]), "r"(a[1]), "r"(a[2]), "r"(a[3]), "r"(b[0]), "r"(b[1]));
}

// ---------------- tf32 tensor-core GEMM (unchanged from R4) ----------------
template <bool HEAD>
__device__ __forceinline__ void tc_gemm(const float* __restrict__ A,
                                        const float* __restrict__ W,
                                        const float* __restrict__ bias,
                                        float* __restrict__ C)
{
    extern __shared__ uint32_t dsm[];

    const int tid = threadIdx.x;
    const int wid = tid >> 5;
    const int lid = tid & 31;
    const int g   = lid >> 2;
    const int tig = lid & 3;
    const int warp_m = wid >> 2;
    const int warp_n = wid & 3;
    const int m0 = blockIdx.y * 128;
    const int n0 = blockIdx.x * 128;

    const int lr = tid >> 2;
    const int lc = tid & 3;

    float acc[4][4][4];
#pragma unroll
    for (int mi = 0; mi < 4; mi++)
#pragma unroll
        for (int ni = 0; ni < 4; ni++)
#pragma unroll
            for (int r = 0; r < 4; r++) acc[mi][ni][r] = 0.f;

    float4 pa[2], pb[2];

#pragma unroll
    for (int it = 0; it < 2; it++) {
        const int r = lr + it * 64;
        pa[it] = *(const float4*)(A + (size_t)(m0 + r) * D_MODEL + lc * 4);
        pb[it] = *(const float4*)(W + (size_t)(n0 + r) * D_MODEL + lc * 4);
    }
    {
        uint32_t* as = dsm;
        uint32_t* bs = dsm + TILE_WORDS;
#pragma unroll
        for (int it = 0; it < 2; it++) {
            const int r = lr + it * 64;
            uint4 ua, ub;
            ua.x = f2tf32(pa[it].x); ua.y = f2tf32(pa[it].y); ua.z = f2tf32(pa[it].z); ua.w = f2tf32(pa[it].w);
            ub.x = f2tf32(pb[it].x); ub.y = f2tf32(pb[it].y); ub.z = f2tf32(pb[it].z); ub.w = f2tf32(pb[it].w);
            *(uint4*)(as + r * RSTRIDE + lc * 4) = ua;
            *(uint4*)(bs + r * RSTRIDE + lc * 4) = ub;
        }
    }
    __syncthreads();

    int cur = 0;
    for (int c = 0; c < NCHUNK; c++) {
        if (c + 1 < NCHUNK) {
            const int k0 = (c + 1) * BK;
#pragma unroll
            for (int it = 0; it < 2; it++) {
                const int r = lr + it * 64;
                pa[it] = *(const float4*)(A + (size_t)(m0 + r) * D_MODEL + k0 + lc * 4);
                pb[it] = *(const float4*)(W + (size_t)(n0 + r) * D_MODEL + k0 + lc * 4);
            }
        }

        const uint32_t* as = dsm + cur * 2 * TILE_WORDS;
        const uint32_t* bs = as + TILE_WORDS;
#pragma unroll
        for (int ks = 0; ks < 2; ks++) {
            uint32_t af[4][4], bf[4][2];
#pragma unroll
            for (int mi = 0; mi < 4; mi++) {
                const uint32_t* p = as + (warp_m * 64 + mi * 16 + g) * RSTRIDE + ks * 8 + tig;
                af[mi][0] = p[0];
                af[mi][1] = p[8 * RSTRIDE];
                af[mi][2] = p[4];
                af[mi][3] = p[8 * RSTRIDE + 4];
            }
#pragma unroll
            for (int ni = 0; ni < 4; ni++) {
                const uint32_t* p = bs + (warp_n * 32 + ni * 8 + g) * RSTRIDE + ks * 8 + tig;
                bf[ni][0] = p[0];
                bf[ni][1] = p[4];
            }
#pragma unroll
            for (int mi = 0; mi < 4; mi++)
#pragma unroll
                for (int ni = 0; ni < 4; ni++)
                    mma_tf32_16x8x8(acc[mi][ni], af[mi], bf[ni]);
        }

        if (c + 1 < NCHUNK) {
            uint32_t* nas = dsm + (cur ^ 1) * 2 * TILE_WORDS;
            uint32_t* nbs = nas + TILE_WORDS;
#pragma unroll
            for (int it = 0; it < 2; it++) {
                const int r = lr + it * 64;
                uint4 ua, ub;
                ua.x = f2tf32(pa[it].x); ua.y = f2tf32(pa[it].y); ua.z = f2tf32(pa[it].z); ua.w = f2tf32(pa[it].w);
                ub.x = f2tf32(pb[it].x); ub.y = f2tf32(pb[it].y); ub.z = f2tf32(pb[it].z); ub.w = f2tf32(pb[it].w);
                *(uint4*)(nas + r * RSTRIDE + lc * 4) = ua;
                *(uint4*)(nbs + r * RSTRIDE + lc * 4) = ub;
            }
        }
        __syncthreads();
        cur ^= 1;
    }

#pragma unroll
    for (int mi = 0; mi < 4; mi++) {
#pragma unroll
        for (int rr = 0; rr < 2; rr++) {
            const int m = m0 + warp_m * 64 + mi * 16 + g + rr * 8;
            const int bb = m >> 11;
            const int l  = m & (SEQ - 1);
#pragma unroll
            for (int ni = 0; ni < 4; ni++) {
#pragma unroll
                for (int cc = 0; cc < 2; cc++) {
                    const int n = n0 + warp_n * 32 + ni * 8 + 2 * tig + cc;
                    const float v = acc[mi][ni][rr * 2 + cc] + bias[n];
                    if (HEAD) {
                        const int h  = n >> 6;
                        const int dk = n & (D_K - 1);
                        C[((size_t)(bb * N_HEADS + h) * SEQ + l) * D_K + dk] = v;
                    } else {
                        C[(size_t)m * D_MODEL + n] = v;
                    }
                }
            }
        }
    }
}

__global__ void __launch_bounds__(256, 2) proj_kernel(
    const float* __restrict__ Q,  const float* __restrict__ K,  const float* __restrict__ V,
    const float* __restrict__ Wq, const float* __restrict__ Wk, const float* __restrict__ Wv,
    const float* __restrict__ bq, const float* __restrict__ bk, const float* __restrict__ bv)
{
    const int z = blockIdx.z;
    if (z == 0)      tc_gemm<true>(Q, Wq, bq, g_qh);
    else if (z == 1) tc_gemm<true>(K, Wk, bk, g_kh);
    else             tc_gemm<true>(V, Wv, bv, g_vh);
}

__global__ void __launch_bounds__(256, 2) out_kernel(
    const float* __restrict__ Wo, const float* __restrict__ bo, float* __restrict__ out)
{
    tc_gemm<false>(g_att, Wo, bo, out);
}

// ---------------- tensor-core flash attention ----------------
// CTA: 128 q-rows of one (b,h); kv tiles of 128; online softmax.
// S-MMA: warps 2m x 4n (64x32 tile).  PV-MMA: warps 4m x 2n (32x32 tile).
__global__ void __launch_bounds__(256) attn_kernel()
{
    extern __shared__ uint32_t dsm[];
    float* m_s  = (float*)(dsm + A_MS);
    float* l_s  = (float*)(dsm + A_LS);
    float* cf_s = (float*)(dsm + A_CF);

    const int tid = threadIdx.x;
    const int wid = tid >> 5;
    const int lid = tid & 31;
    const int g   = lid >> 2;
    const int tig = lid & 3;
    const int warp_m = wid >> 2;          // S phase: 0..1
    const int warp_n = wid & 3;           // S phase: 0..3
    const int pwarp_m = wid >> 1;         // PV phase: 0..3
    const int pwarp_n = wid & 1;          // PV phase: 0..1

    const int bh = blockIdx.y;
    const int q0 = (gridDim.x - 1 - blockIdx.x) * 128;   // heavy blocks first
    const int bb = bh >> 4;
    const int h  = bh & 15;

    // ---- load Q tile (128x64) -> smem tf32 ----
    const float* qb = g_qh + ((size_t)bh * SEQ + q0) * D_K;
#pragma unroll
    for (int it = 0; it < 8; it++) {
        const int slot = tid + it * 256;       // 2048 = 128 rows x 16 float4
        const int r  = slot >> 4;
        const int c4 = slot & 15;
        const float4 f = *(const float4*)(qb + (size_t)r * D_K + c4 * 4);
        uint32_t* p = dsm + A_QS + r * AST + c4 * 4;
        p[0] = f2tf32(f.x); p[1] = f2tf32(f.y); p[2] = f2tf32(f.z); p[3] = f2tf32(f.w);
    }
    if (tid < 128) { m_s[tid] = -1e30f; l_s[tid] = 0.f; }

    float oacc[2][4][4];
#pragma unroll
    for (int mi = 0; mi < 2; mi++)
#pragma unroll
        for (int ni = 0; ni < 4; ni++)
#pragma unroll
            for (int r = 0; r < 4; r++) oacc[mi][ni][r] = 0.f;

    const int ntiles = q0 / 128 + 1;
    for (int t = 0; t < ntiles; t++) {
        const int kv0 = t * 128;
        __syncthreads();   // prev iter done reading Ks/Vt/Ps

        // ---- load K tile (128x64) and V tile transposed (64x128) ----
        const float* kb = g_kh + ((size_t)bh * SEQ + kv0) * D_K;
        const float* vb = g_vh + ((size_t)bh * SEQ + kv0) * D_K;
#pragma unroll
        for (int it = 0; it < 8; it++) {
            const int slot = tid + it * 256;
            const int r  = slot >> 4;          // kv row
            const int c4 = slot & 15;          // d float4
            const float4 fk = *(const float4*)(kb + (size_t)r * D_K + c4 * 4);
            uint32_t* p = dsm + A_KS + r * AST + c4 * 4;
            p[0] = f2tf32(fk.x); p[1] = f2tf32(fk.y); p[2] = f2tf32(fk.z); p[3] = f2tf32(fk.w);
            const float4 fv = *(const float4*)(vb + (size_t)r * D_K + c4 * 4);
            uint32_t* vt = dsm + A_VT + (c4 * 4) * PST + r;
            vt[0]       = f2tf32(fv.x);
            vt[PST]     = f2tf32(fv.y);
            vt[2 * PST] = f2tf32(fv.z);
            vt[3 * PST] = f2tf32(fv.w);
        }
        __syncthreads();

        // ---- S = Q K^T : M=128 N=128 K=64, warps 2m x 4n ----
        {
            float sacc[4][4][4];
#pragma unroll
            for (int mi = 0; mi < 4; mi++)
#pragma unroll
                for (int ni = 0; ni < 4; ni++)
#pragma unroll
                    for (int r = 0; r < 4; r++) sacc[mi][ni][r] = 0.f;

#pragma unroll
            for (int ks = 0; ks < 8; ks++) {
                uint32_t af[4][4], bf[4][2];
#pragma unroll
                for (int mi = 0; mi < 4; mi++) {
                    const uint32_t* p = dsm + A_QS + (warp_m * 64 + mi * 16 + g) * AST + ks * 8 + tig;
                    af[mi][0] = p[0];
                    af[mi][1] = p[8 * AST];
                    af[mi][2] = p[4];
                    af[mi][3] = p[8 * AST + 4];
                }
#pragma unroll
                for (int ni = 0; ni < 4; ni++) {
                    const uint32_t* p = dsm + A_KS + (warp_n * 32 + ni * 8 + g) * AST + ks * 8 + tig;
                    bf[ni][0] = p[0];
                    bf[ni][1] = p[4];
                }
#pragma unroll
                for (int mi = 0; mi < 4; mi++)
#pragma unroll
                    for (int ni = 0; ni < 4; ni++)
                        mma_tf32_16x8x8(sacc[mi][ni], af[mi], bf[ni]);
            }

            // scale + causal mask + store S (fp32) to Ps
            const bool diag = (kv0 == q0);
#pragma unroll
            for (int mi = 0; mi < 4; mi++)
#pragma unroll
                for (int rr = 0; rr < 2; rr++) {
                    const int r = warp_m * 64 + mi * 16 + g + rr * 8;
#pragma unroll
                    for (int ni = 0; ni < 4; ni++)
#pragma unroll
                        for (int cc = 0; cc < 2; cc++) {
                            const int ccol = warp_n * 32 + ni * 8 + 2 * tig + cc;
                            float v = sacc[mi][ni][rr * 2 + cc] * 0.125f;
                            if (diag && ccol > r) v = -1e30f;
                            dsm[A_PS + r * PST + ccol] = __float_as_uint(v);
                        }
                }
        }
        __syncthreads();

        // ---- row softmax (2 threads per row, shfl.bfly partner) ----
        {
            const int srow = tid >> 1;
            const int half = tid & 1;
            uint32_t* prow = dsm + A_PS + srow * PST + half * 64;
            float mx = -1e30f;
#pragma unroll 8
            for (int c = 0; c < 64; c++) mx = fmaxf(mx, __uint_as_float(prow[c]));
            mx = fmaxf(mx, __shfl_xor_sync(0xFFFFFFFFu, mx, 1));
            const float mo = m_s[srow];
            const float mxn = fmaxf(mo, mx);
            float sum = 0.f;
#pragma unroll 8
            for (int c = 0; c < 64; c++) {
                const float p = __expf(__uint_as_float(prow[c]) - mxn);
                sum += p;
                prow[c] = f2tf32(p);
            }
            sum += __shfl_xor_sync(0xFFFFFFFFu, sum, 1);
            if (half == 0) {
                const float cf = __expf(mo - mxn);
                l_s[srow] = l_s[srow] * cf + sum;
                m_s[srow] = mxn;
                cf_s[srow] = cf;
            }
        }
        __syncthreads();

        // ---- O = O*cf + P @ V : M=128 N=64 K=128, warps 4m x 2n ----
#pragma unroll
        for (int mi = 0; mi < 2; mi++)
#pragma unroll
            for (int rr = 0; rr < 2; rr++) {
                const float cf = cf_s[pwarp_m * 32 + mi * 16 + rr * 8 + g];
#pragma unroll
                for (int ni = 0; ni < 4; ni++)
#pragma unroll
                    for (int cc = 0; cc < 2; cc++)
                        oacc[mi][ni][rr * 2 + cc] *= cf;
            }
#pragma unroll
        for (int ks = 0; ks < 16; ks++) {
            uint32_t af[2][4], bf[4][2];
#pragma unroll
            for (int mi = 0; mi < 2; mi++) {
                const uint32_t* p = dsm + A_PS + (pwarp_m * 32 + mi * 16 + g) * PST + ks * 8 + tig;
                af[mi][0] = p[0];
                af[mi][1] = p[8 * PST];
                af[mi][2] = p[4];
                af[mi][3] = p[8 * PST + 4];
            }
#pragma unroll
            for (int ni = 0; ni < 4; ni++) {
                const uint32_t* p = dsm + A_VT + (pwarp_n * 32 + ni * 8 + g) * PST + ks * 8 + tig;
                bf[ni][0] = p[0];
                bf[ni][1] = p[4];
            }
#pragma unroll
            for (int mi = 0; mi < 2; mi++)
#pragma unroll
                for (int ni = 0; ni < 4; ni++)
                    mma_tf32_16x8x8(oacc[mi][ni], af[mi], bf[ni]);
        }
    }

    // ---- epilogue: normalize, write [B,L,D] ----
#pragma unroll
    for (int mi = 0; mi < 2; mi++)
#pragma unroll
        for (int rr = 0; rr < 2; rr++) {
            const int r = pwarp_m * 32 + mi * 16 + rr * 8 + g;
            const float inv = 1.f / l_s[r];
            const int q = q0 + r;
#pragma unroll
            for (int ni = 0; ni < 4; ni++)
#pragma unroll
                for (int cc = 0; cc < 2; cc++) {
                    const int d = pwarp_n * 32 + ni * 8 + 2 * tig + cc;
                    g_att[((size_t)bb * SEQ + q) * D_MODEL + h * D_K + d] =
                        oacc[mi][ni][rr * 2 + cc] * inv;
                }
        }
}

// ---------------- launch ----------------
extern "C" void kernel_launch(void* const* d_in, const int* in_sizes, int n_in,
                              void* d_out, int out_size)
{
    const float* Q = (const float*)d_in[0];
    const float* K = (const float*)d_in[1];
    const float* V = (const float*)d_in[2];
    const int wb = (n_in > 3 && in_sizes[3] == SEQ * SEQ) ? 4 : 3;
    const float* Wq = (const float*)d_in[wb + 0];
    const float* bq = (const float*)d_in[wb + 1];
    const float* Wk = (const float*)d_in[wb + 2];
    const float* bk = (const float*)d_in[wb + 3];
    const float* Wv = (const float*)d_in[wb + 4];
    const float* bv = (const float*)d_in[wb + 5];
    const float* Wo = (const float*)d_in[wb + 6];
    const float* bo = (const float*)d_in[wb + 7];
    float* out = (float*)d_out;

    cudaFuncSetAttribute(proj_kernel, cudaFuncAttributeMaxDynamicSharedMemorySize, DSMEM_BYTES);
    cudaFuncSetAttribute(out_kernel,  cudaFuncAttributeMaxDynamicSharedMemorySize, DSMEM_BYTES);
    cudaFuncSetAttribute(attn_kernel, cudaFuncAttributeMaxDynamicSharedMemorySize, ATTN_SMEM_BYTES);

    dim3 blk(256);
    proj_kernel<<<dim3(D_MODEL / 128, M_TOTAL / 128, 3), blk, DSMEM_BYTES>>>(
        Q, K, V, Wq, Wk, Wv, bq, bk, bv);
    attn_kernel<<<dim3(SEQ / 128, BATCH * N_HEADS), blk, ATTN_SMEM_BYTES>>>();
    out_kernel<<<dim3(D_MODEL / 128, M_TOTAL / 128), blk, DSMEM_BYTES>>>(Wo, bo, out);
}

// round 6
// speedup vs baseline: 2.9798x; 1.0506x over previous
#include <cuda_runtime.h>
#include <math.h>
#include <stdint.h>

#define D_MODEL 1024
#define N_HEADS 16
#define D_K     64
#define BATCH   4
#define SEQ     2048
#define M_TOTAL (BATCH * SEQ)   // 8192

// GEMM tiling
#define BK      16
#define NCHUNK  (D_MODEL / BK)        // 64
#define RSTRIDE 20                    // padded row stride in words
#define TILE_WORDS (128 * RSTRIDE)    // per matrix per stage
#define DSMEM_BYTES (2 * 2 * TILE_WORDS * 4)   // 40960 B

// attention tiling
#define AST 68     // Q/K row stride words
#define PST 132    // P/Vt row stride words
#define A_QS 0
#define A_KS (128 * AST)
#define A_VT (A_KS + 128 * AST)
#define A_PS (A_VT + 64 * PST)
#define A_MS (A_PS + 128 * PST)
#define A_LS (A_MS + 128)
#define A_CF (A_LS + 128)
#define ATTN_WORDS (A_CF + 128)
#define ATTN_SMEM_BYTES (ATTN_WORDS * 4)  // 172544

// ---------------- scratch (device globals: allocation-free) ----------------
__device__ float g_qh[BATCH * N_HEADS * SEQ * D_K];   // [B,H,L,Dk]
__device__ float g_kh[BATCH * N_HEADS * SEQ * D_K];
__device__ float g_vh[BATCH * N_HEADS * SEQ * D_K];
__device__ float g_att[M_TOTAL * D_MODEL];            // [B,L,D]

// ---------------- helpers ----------------
__device__ __forceinline__ uint32_t f2tf32(float x) {
    uint32_t r; asm("cvt.rna.tf32.f32 %0, %1;" : "=r"(r) : "f"(x)); return r;
}
__device__ __forceinline__ void mma_tf32_16x8x8(float* c, const uint32_t* a, const uint32_t* b) {
    asm volatile(
        "mma.sync.aligned.m16n8k8.row.col.f32.tf32.tf32.f32 "
        "{%0,%1,%2,%3}, {%4,%5,%6,%7}, {%8,%9}, {%0,%1,%2,%3};"
        : "+f"(c[0]), "+f"(c[1]), "+f"(c[2]), "+f"(c[3])
        : "r"(a[0]), "r"(a[1]), "r"(a[2]), "r"(a[3]), "r"(b[0]), "r"(b[1]));
}
// ldmatrix x4: four 8x8 b16 matrices = one m16n8k8 tf32 A-fragment.
// lanes 0-7: rows of quad (m0..7, k0..3); 8-15: (m8..15, k0..3);
// 16-23: (m0..7, k4..7); 24-31: (m8..15, k4..7).
__device__ __forceinline__ void ldsm_x4(uint32_t* r, uint32_t saddr) {
    asm volatile("ldmatrix.sync.aligned.m8n8.x4.shared.b16 {%0,%1,%2,%3}, [%4];"
        : "=r"(r[0]), "=r"(r[1]), "=r"(r[2]), "=r"(r[3]) : "r"(saddr));
}
// ldmatrix x2: one m16n8k8 tf32 B-fragment (b0,b1).
// lanes 0-7: rows (n0..7, k0..3); lanes 8-15: (n0..7, k4..7).
__device__ __forceinline__ void ldsm_x2(uint32_t* r, uint32_t saddr) {
    asm volatile("ldmatrix.sync.aligned.m8n8.x2.shared.b16 {%0,%1}, [%2];"
        : "=r"(r[0]), "=r"(r[1]) : "r"(saddr));
}

// ---------------- tf32 tensor-core GEMM: C[m][n] = sum_k A[m][k]*W[n][k] + bias[n] ----------------
template <bool HEAD>
__device__ __forceinline__ void tc_gemm(const float* __restrict__ A,
                                        const float* __restrict__ W,
                                        const float* __restrict__ bias,
                                        float* __restrict__ C)
{
    extern __shared__ uint32_t dsm[];
    const uint32_t smem_b = (uint32_t)__cvta_generic_to_shared(dsm);

    const int tid = threadIdx.x;
    const int wid = tid >> 5;
    const int lid = tid & 31;
    const int g   = lid >> 2;
    const int tig = lid & 3;
    const int warp_m = wid >> 2;
    const int warp_n = wid & 3;
    const int m0 = blockIdx.y * 128;
    const int n0 = blockIdx.x * 128;

    // ldmatrix per-lane row/col-offset (words)
    const int a_row  = lid & 15;
    const int a_coff = (lid >> 4) * 4;
    const int b_row  = lid & 7;
    const int b_coff = ((lid >> 3) & 1) * 4;

    const int lr = tid >> 2;
    const int lc = tid & 3;

    float acc[4][4][4];
#pragma unroll
    for (int mi = 0; mi < 4; mi++)
#pragma unroll
        for (int ni = 0; ni < 4; ni++)
#pragma unroll
            for (int r = 0; r < 4; r++) acc[mi][ni][r] = 0.f;

    float4 pa[2], pb[2];

#pragma unroll
    for (int it = 0; it < 2; it++) {
        const int r = lr + it * 64;
        pa[it] = *(const float4*)(A + (size_t)(m0 + r) * D_MODEL + lc * 4);
        pb[it] = *(const float4*)(W + (size_t)(n0 + r) * D_MODEL + lc * 4);
    }
    {
        uint32_t* as = dsm;
        uint32_t* bs = dsm + TILE_WORDS;
#pragma unroll
        for (int it = 0; it < 2; it++) {
            const int r = lr + it * 64;
            uint4 ua, ub;
            ua.x = f2tf32(pa[it].x); ua.y = f2tf32(pa[it].y); ua.z = f2tf32(pa[it].z); ua.w = f2tf32(pa[it].w);
            ub.x = f2tf32(pb[it].x); ub.y = f2tf32(pb[it].y); ub.z = f2tf32(pb[it].z); ub.w = f2tf32(pb[it].w);
            *(uint4*)(as + r * RSTRIDE + lc * 4) = ua;
            *(uint4*)(bs + r * RSTRIDE + lc * 4) = ub;
        }
    }
    __syncthreads();

    int cur = 0;
    for (int c = 0; c < NCHUNK; c++) {
        if (c + 1 < NCHUNK) {
            const int k0 = (c + 1) * BK;
#pragma unroll
            for (int it = 0; it < 2; it++) {
                const int r = lr + it * 64;
                pa[it] = *(const float4*)(A + (size_t)(m0 + r) * D_MODEL + k0 + lc * 4);
                pb[it] = *(const float4*)(W + (size_t)(n0 + r) * D_MODEL + k0 + lc * 4);
            }
        }

        const uint32_t stA = (uint32_t)(cur * 2 * TILE_WORDS);
        const uint32_t stB = stA + TILE_WORDS;
#pragma unroll
        for (int ks = 0; ks < 2; ks++) {
            uint32_t af[4][4], bf[4][2];
#pragma unroll
            for (int mi = 0; mi < 4; mi++)
                ldsm_x4(af[mi], smem_b + ((stA + (uint32_t)((warp_m * 64 + mi * 16 + a_row) * RSTRIDE + ks * 8 + a_coff)) << 2));
#pragma unroll
            for (int ni = 0; ni < 4; ni++)
                ldsm_x2(bf[ni], smem_b + ((stB + (uint32_t)((warp_n * 32 + ni * 8 + b_row) * RSTRIDE + ks * 8 + b_coff)) << 2));
#pragma unroll
            for (int mi = 0; mi < 4; mi++)
#pragma unroll
                for (int ni = 0; ni < 4; ni++)
                    mma_tf32_16x8x8(acc[mi][ni], af[mi], bf[ni]);
        }

        if (c + 1 < NCHUNK) {
            uint32_t* nas = dsm + (cur ^ 1) * 2 * TILE_WORDS;
            uint32_t* nbs = nas + TILE_WORDS;
#pragma unroll
            for (int it = 0; it < 2; it++) {
                const int r = lr + it * 64;
                uint4 ua, ub;
                ua.x = f2tf32(pa[it].x); ua.y = f2tf32(pa[it].y); ua.z = f2tf32(pa[it].z); ua.w = f2tf32(pa[it].w);
                ub.x = f2tf32(pb[it].x); ub.y = f2tf32(pb[it].y); ub.z = f2tf32(pb[it].z); ub.w = f2tf32(pb[it].w);
                *(uint4*)(nas + r * RSTRIDE + lc * 4) = ua;
                *(uint4*)(nbs + r * RSTRIDE + lc * 4) = ub;
            }
        }
        __syncthreads();
        cur ^= 1;
    }

#pragma unroll
    for (int mi = 0; mi < 4; mi++) {
#pragma unroll
        for (int rr = 0; rr < 2; rr++) {
            const int m = m0 + warp_m * 64 + mi * 16 + g + rr * 8;
            const int bb = m >> 11;
            const int l  = m & (SEQ - 1);
#pragma unroll
            for (int ni = 0; ni < 4; ni++) {
#pragma unroll
                for (int cc = 0; cc < 2; cc++) {
                    const int n = n0 + warp_n * 32 + ni * 8 + 2 * tig + cc;
                    const float v = acc[mi][ni][rr * 2 + cc] + bias[n];
                    if (HEAD) {
                        const int h  = n >> 6;
                        const int dk = n & (D_K - 1);
                        C[((size_t)(bb * N_HEADS + h) * SEQ + l) * D_K + dk] = v;
                    } else {
                        C[(size_t)m * D_MODEL + n] = v;
                    }
                }
            }
        }
    }
}

__global__ void __launch_bounds__(256, 2) proj_kernel(
    const float* __restrict__ Q,  const float* __restrict__ K,  const float* __restrict__ V,
    const float* __restrict__ Wq, const float* __restrict__ Wk, const float* __restrict__ Wv,
    const float* __restrict__ bq, const float* __restrict__ bk, const float* __restrict__ bv)
{
    const int z = blockIdx.z;
    if (z == 0)      tc_gemm<true>(Q, Wq, bq, g_qh);
    else if (z == 1) tc_gemm<true>(K, Wk, bk, g_kh);
    else             tc_gemm<true>(V, Wv, bv, g_vh);
}

__global__ void __launch_bounds__(256, 2) out_kernel(
    const float* __restrict__ Wo, const float* __restrict__ bo, float* __restrict__ out)
{
    tc_gemm<false>(g_att, Wo, bo, out);
}

// ---------------- tensor-core flash attention ----------------
__global__ void __launch_bounds__(256) attn_kernel()
{
    extern __shared__ uint32_t dsm[];
    const uint32_t smem_b = (uint32_t)__cvta_generic_to_shared(dsm);
    float* m_s  = (float*)(dsm + A_MS);
    float* l_s  = (float*)(dsm + A_LS);
    float* cf_s = (float*)(dsm + A_CF);

    const int tid = threadIdx.x;
    const int wid = tid >> 5;
    const int lid = tid & 31;
    const int g   = lid >> 2;
    const int tig = lid & 3;
    const int warp_m = wid >> 2;          // S phase
    const int warp_n = wid & 3;
    const int pwarp_m = wid >> 1;         // PV phase
    const int pwarp_n = wid & 1;

    const int a_row  = lid & 15;
    const int a_coff = (lid >> 4) * 4;
    const int b_row  = lid & 7;
    const int b_coff = ((lid >> 3) & 1) * 4;

    const int bh = blockIdx.y;
    const int q0 = (gridDim.x - 1 - blockIdx.x) * 128;
    const int bb = bh >> 4;
    const int h  = bh & 15;

    // ---- load Q tile (128x64) -> smem tf32 ----
    const float* qb = g_qh + ((size_t)bh * SEQ + q0) * D_K;
#pragma unroll
    for (int it = 0; it < 8; it++) {
        const int slot = tid + it * 256;
        const int r  = slot >> 4;
        const int c4 = slot & 15;
        const float4 f = *(const float4*)(qb + (size_t)r * D_K + c4 * 4);
        uint32_t* p = dsm + A_QS + r * AST + c4 * 4;
        p[0] = f2tf32(f.x); p[1] = f2tf32(f.y); p[2] = f2tf32(f.z); p[3] = f2tf32(f.w);
    }
    if (tid < 128) { m_s[tid] = -1e30f; l_s[tid] = 0.f; }

    float oacc[2][4][4];
#pragma unroll
    for (int mi = 0; mi < 2; mi++)
#pragma unroll
        for (int ni = 0; ni < 4; ni++)
#pragma unroll
            for (int r = 0; r < 4; r++) oacc[mi][ni][r] = 0.f;

    const int ntiles = q0 / 128 + 1;
    for (int t = 0; t < ntiles; t++) {
        const int kv0 = t * 128;
        __syncthreads();

        // ---- load K tile (128x64) and V tile transposed (64x128) ----
        const float* kb = g_kh + ((size_t)bh * SEQ + kv0) * D_K;
        const float* vb = g_vh + ((size_t)bh * SEQ + kv0) * D_K;
#pragma unroll
        for (int it = 0; it < 8; it++) {
            const int slot = tid + it * 256;
            const int r  = slot >> 4;
            const int c4 = slot & 15;
            const float4 fk = *(const float4*)(kb + (size_t)r * D_K + c4 * 4);
            uint32_t* p = dsm + A_KS + r * AST + c4 * 4;
            p[0] = f2tf32(fk.x); p[1] = f2tf32(fk.y); p[2] = f2tf32(fk.z); p[3] = f2tf32(fk.w);
            const float4 fv = *(const float4*)(vb + (size_t)r * D_K + c4 * 4);
            uint32_t* vt = dsm + A_VT + (c4 * 4) * PST + r;
            vt[0]       = f2tf32(fv.x);
            vt[PST]     = f2tf32(fv.y);
            vt[2 * PST] = f2tf32(fv.z);
            vt[3 * PST] = f2tf32(fv.w);
        }
        __syncthreads();

        // ---- S = Q K^T : M=128 N=128 K=64, warps 2m x 4n ----
        {
            float sacc[4][4][4];
#pragma unroll
            for (int mi = 0; mi < 4; mi++)
#pragma unroll
                for (int ni = 0; ni < 4; ni++)
#pragma unroll
                    for (int r = 0; r < 4; r++) sacc[mi][ni][r] = 0.f;

#pragma unroll
            for (int ks = 0; ks < 8; ks++) {
                uint32_t af[4][4], bf[4][2];
#pragma unroll
                for (int mi = 0; mi < 4; mi++)
                    ldsm_x4(af[mi], smem_b + ((uint32_t)(A_QS + (warp_m * 64 + mi * 16 + a_row) * AST + ks * 8 + a_coff) << 2));
#pragma unroll
                for (int ni = 0; ni < 4; ni++)
                    ldsm_x2(bf[ni], smem_b + ((uint32_t)(A_KS + (warp_n * 32 + ni * 8 + b_row) * AST + ks * 8 + b_coff) << 2));
#pragma unroll
                for (int mi = 0; mi < 4; mi++)
#pragma unroll
                    for (int ni = 0; ni < 4; ni++)
                        mma_tf32_16x8x8(sacc[mi][ni], af[mi], bf[ni]);
            }

            const bool diag = (kv0 == q0);
#pragma unroll
            for (int mi = 0; mi < 4; mi++)
#pragma unroll
                for (int rr = 0; rr < 2; rr++) {
                    const int r = warp_m * 64 + mi * 16 + g + rr * 8;
#pragma unroll
                    for (int ni = 0; ni < 4; ni++)
#pragma unroll
                        for (int cc = 0; cc < 2; cc++) {
                            const int ccol = warp_n * 32 + ni * 8 + 2 * tig + cc;
                            float v = sacc[mi][ni][rr * 2 + cc] * 0.125f;
                            if (diag && ccol > r) v = -1e30f;
                            dsm[A_PS + r * PST + ccol] = __float_as_uint(v);
                        }
                }
        }
        __syncthreads();

        // ---- row softmax (2 threads per row) ----
        {
            const int srow = tid >> 1;
            const int half = tid & 1;
            uint32_t* prow = dsm + A_PS + srow * PST + half * 64;
            float mx = -1e30f;
#pragma unroll 8
            for (int c = 0; c < 64; c++) mx = fmaxf(mx, __uint_as_float(prow[c]));
            mx = fmaxf(mx, __shfl_xor_sync(0xFFFFFFFFu, mx, 1));
            const float mo = m_s[srow];
            const float mxn = fmaxf(mo, mx);
            float sum = 0.f;
#pragma unroll 8
            for (int c = 0; c < 64; c++) {
                const float p = __expf(__uint_as_float(prow[c]) - mxn);
                sum += p;
                prow[c] = f2tf32(p);
            }
            sum += __shfl_xor_sync(0xFFFFFFFFu, sum, 1);
            if (half == 0) {
                const float cf = __expf(mo - mxn);
                l_s[srow] = l_s[srow] * cf + sum;
                m_s[srow] = mxn;
                cf_s[srow] = cf;
            }
        }
        __syncthreads();

        // ---- O = O*cf + P @ V : M=128 N=64 K=128, warps 4m x 2n ----
#pragma unroll
        for (int mi = 0; mi < 2; mi++)
#pragma unroll
            for (int rr = 0; rr < 2; rr++) {
                const float cf = cf_s[pwarp_m * 32 + mi * 16 + rr * 8 + g];
#pragma unroll
                for (int ni = 0; ni < 4; ni++)
#pragma unroll
                    for (int cc = 0; cc < 2; cc++)
                        oacc[mi][ni][rr * 2 + cc] *= cf;
            }
#pragma unroll
        for (int ks = 0; ks < 16; ks++) {
            uint32_t af[2][4], bf[4][2];
#pragma unroll
            for (int mi = 0; mi < 2; mi++)
                ldsm_x4(af[mi], smem_b + ((uint32_t)(A_PS + (pwarp_m * 32 + mi * 16 + a_row) * PST + ks * 8 + a_coff) << 2));
#pragma unroll
            for (int ni = 0; ni < 4; ni++)
                ldsm_x2(bf[ni], smem_b + ((uint32_t)(A_VT + (pwarp_n * 32 + ni * 8 + b_row) * PST + ks * 8 + b_coff) << 2));
#pragma unroll
            for (int mi = 0; mi < 2; mi++)
#pragma unroll
                for (int ni = 0; ni < 4; ni++)
                    mma_tf32_16x8x8(oacc[mi][ni], af[mi], bf[ni]);
        }
    }

    // ---- epilogue: normalize, write [B,L,D] ----
#pragma unroll
    for (int mi = 0; mi < 2; mi++)
#pragma unroll
        for (int rr = 0; rr < 2; rr++) {
            const int r = pwarp_m * 32 + mi * 16 + rr * 8 + g;
            const float inv = 1.f / l_s[r];
            const int q = q0 + r;
#pragma unroll
            for (int ni = 0; ni < 4; ni++)
#pragma unroll
                for (int cc = 0; cc < 2; cc++) {
                    const int d = pwarp_n * 32 + ni * 8 + 2 * tig + cc;
                    g_att[((size_t)bb * SEQ + q) * D_MODEL + h * D_K + d] =
                        oacc[mi][ni][rr * 2 + cc] * inv;
                }
        }
}

// ---------------- launch ----------------
extern "C" void kernel_launch(void* const* d_in, const int* in_sizes, int n_in,
                              void* d_out, int out_size)
{
    const float* Q = (const float*)d_in[0];
    const float* K = (const float*)d_in[1];
    const float* V = (const float*)d_in[2];
    const int wb = (n_in > 3 && in_sizes[3] == SEQ * SEQ) ? 4 : 3;
    const float* Wq = (const float*)d_in[wb + 0];
    const float* bq = (const float*)d_in[wb + 1];
    const float* Wk = (const float*)d_in[wb + 2];
    const float* bk = (const float*)d_in[wb + 3];
    const float* Wv = (const float*)d_in[wb + 4];
    const float* bv = (const float*)d_in[wb + 5];
    const float* Wo = (const float*)d_in[wb + 6];
    const float* bo = (const float*)d_in[wb + 7];
    float* out = (float*)d_out;

    cudaFuncSetAttribute(proj_kernel, cudaFuncAttributeMaxDynamicSharedMemorySize, DSMEM_BYTES);
    cudaFuncSetAttribute(out_kernel,  cudaFuncAttributeMaxDynamicSharedMemorySize, DSMEM_BYTES);
    cudaFuncSetAttribute(attn_kernel, cudaFuncAttributeMaxDynamicSharedMemorySize, ATTN_SMEM_BYTES);

    dim3 blk(256);
    proj_kernel<<<dim3(D_MODEL / 128, M_TOTAL / 128, 3), blk, DSMEM_BYTES>>>(
        Q, K, V, Wq, Wk, Wv, bq, bk, bv);
    attn_kernel<<<dim3(SEQ / 128, BATCH * N_HEADS), blk, ATTN_SMEM_BYTES>>>();
    out_kernel<<<dim3(D_MODEL / 128, M_TOTAL / 128), blk, DSMEM_BYTES>>>(Wo, bo, out);
}

// round 7
// speedup vs baseline: 3.7542x; 1.2599x over previous
#include <cuda_runtime.h>
#include <cuda_fp16.h>
#include <math.h>
#include <stdint.h>

#define D_MODEL 1024
#define N_HEADS 16
#define D_K     64
#define BATCH   4
#define SEQ     2048
#define M_TOTAL (BATCH * SEQ)   // 8192

// ---- GEMM tiling (f16, k-chunk = 16 halves) ----
#define NCHUNK  64
#define RSTW    12                    // row stride in words (24 halves; banks 12r%32 distinct)
#define TILE_W  (128 * RSTW)          // 1536 words per matrix per stage
#define DSMEM_BYTES (2 * 2 * TILE_W * 4)   // 24576 B

// ---- attention tiling (words) ----
#define QST 36     // Q/K/V row stride words (64 halves + pad)
#define SST 132    // S fp32 row stride words
#define PSTW 68    // P row stride words (128 halves + pad)
#define A_QS 0
#define A_KS (128 * QST)              // 4608
#define A_VS (A_KS + 128 * QST)       // 9216
#define A_SS (A_VS + 128 * QST)       // 13824
#define A_PH (A_SS + 128 * SST)       // 30720
#define A_MS (A_PH + 128 * PSTW)      // 39424
#define A_LS (A_MS + 128)
#define A_CF (A_LS + 128)
#define ATTN_WORDS (A_CF + 128)       // 39808
#define ATTN_SMEM_BYTES (ATTN_WORDS * 4)   // 159232

// ---------------- scratch (device globals: allocation-free) ----------------
__device__ __half g_qh[BATCH * N_HEADS * SEQ * D_K];   // [B,H,L,Dk] f16
__device__ __half g_kh[BATCH * N_HEADS * SEQ * D_K];
__device__ __half g_vh[BATCH * N_HEADS * SEQ * D_K];
__device__ __half g_att[M_TOTAL * D_MODEL];            // [B,L,D] f16

// ---------------- helpers ----------------
__device__ __forceinline__ void mma_f16_16x8x16(float* c, const uint32_t* a, const uint32_t* b) {
    asm volatile(
        "mma.sync.aligned.m16n8k16.row.col.f32.f16.f16.f32 "
        "{%0,%1,%2,%3}, {%4,%5,%6,%7}, {%8,%9}, {%0,%1,%2,%3};"
        : "+f"(c[0]), "+f"(c[1]), "+f"(c[2]), "+f"(c[3])
        : "r"(a[0]), "r"(a[1]), "r"(a[2]), "r"(a[3]), "r"(b[0]), "r"(b[1]));
}
__device__ __forceinline__ void ldsm_x4(uint32_t* r, uint32_t saddr) {
    asm volatile("ldmatrix.sync.aligned.m8n8.x4.shared.b16 {%0,%1,%2,%3}, [%4];"
        : "=r"(r[0]), "=r"(r[1]), "=r"(r[2]), "=r"(r[3]) : "r"(saddr));
}
__device__ __forceinline__ void ldsm_x2(uint32_t* r, uint32_t saddr) {
    asm volatile("ldmatrix.sync.aligned.m8n8.x2.shared.b16 {%0,%1}, [%2];"
        : "=r"(r[0]), "=r"(r[1]) : "r"(saddr));
}
__device__ __forceinline__ void ldsm_x2_trans(uint32_t* r, uint32_t saddr) {
    asm volatile("ldmatrix.sync.aligned.m8n8.x2.trans.shared.b16 {%0,%1}, [%2];"
        : "=r"(r[0]), "=r"(r[1]) : "r"(saddr));
}
__device__ __forceinline__ uint32_t pack_h2(float x, float y) {
    __half2 h = __floats2half2_rn(x, y);
    return *(uint32_t*)&h;
}

// ---------------- f16 tensor-core GEMM: C[m][n] = sum_k A[m][k]*W[n][k] + bias[n] ----------------
// Block 128x128, 8 warps (2m x 4n), warp tile 64x32, m16n8k16. W is fp32, converted on load.
// AHALF: A is __half (g_att); else fp32 converted on load.
template <bool AHALF, bool HEAD>
__device__ __forceinline__ void tc_gemm(const void* Ap, const float* __restrict__ W,
                                        const float* __restrict__ bias, void* Cp)
{
    extern __shared__ uint32_t dsm[];
    const uint32_t smem_b = (uint32_t)__cvta_generic_to_shared(dsm);
    const float*  Af = (const float*)Ap;
    const __half* Ah = (const __half*)Ap;

    const int tid = threadIdx.x;
    const int wid = tid >> 5;
    const int lid = tid & 31;
    const int g   = lid >> 2;
    const int tig = lid & 3;
    const int warp_m = wid >> 2;
    const int warp_n = wid & 3;
    const int m0 = blockIdx.y * 128;
    const int n0 = blockIdx.x * 128;

    const int a_row  = lid & 15;
    const int a_coff = (lid >> 4) * 4;          // words (16B = 8 halves)
    const int b_row  = lid & 7;
    const int b_coff = ((lid >> 3) & 1) * 4;

    // loader: 256 slots of 8 halves (16B) per matrix per chunk
    const int lr = tid >> 1;            // row 0..127
    const int lc = tid & 1;             // 8-half group 0..1

    float acc[4][4][4];
#pragma unroll
    for (int mi = 0; mi < 4; mi++)
#pragma unroll
        for (int ni = 0; ni < 4; ni++)
#pragma unroll
            for (int r = 0; r < 4; r++) acc[mi][ni][r] = 0.f;

    float4 fa0, fa1, fb0, fb1;
    uint4  ha;

    // ---- prologue: chunk 0 ----
    if (AHALF) {
        ha = *(const uint4*)(Ah + (size_t)(m0 + lr) * D_MODEL + lc * 8);
    } else {
        fa0 = *(const float4*)(Af + (size_t)(m0 + lr) * D_MODEL + lc * 8);
        fa1 = *(const float4*)(Af + (size_t)(m0 + lr) * D_MODEL + lc * 8 + 4);
    }
    fb0 = *(const float4*)(W + (size_t)(n0 + lr) * D_MODEL + lc * 8);
    fb1 = *(const float4*)(W + (size_t)(n0 + lr) * D_MODEL + lc * 8 + 4);
    {
        uint4 ua, ub;
        if (AHALF) ua = ha;
        else { ua.x = pack_h2(fa0.x, fa0.y); ua.y = pack_h2(fa0.z, fa0.w);
               ua.z = pack_h2(fa1.x, fa1.y); ua.w = pack_h2(fa1.z, fa1.w); }
        ub.x = pack_h2(fb0.x, fb0.y); ub.y = pack_h2(fb0.z, fb0.w);
        ub.z = pack_h2(fb1.x, fb1.y); ub.w = pack_h2(fb1.z, fb1.w);
        *(uint4*)(dsm + lr * RSTW + lc * 4) = ua;
        *(uint4*)(dsm + TILE_W + lr * RSTW + lc * 4) = ub;
    }
    __syncthreads();

    int cur = 0;
    for (int c = 0; c < NCHUNK; c++) {
        if (c + 1 < NCHUNK) {
            const int k0 = (c + 1) * 16;
            if (AHALF) {
                ha = *(const uint4*)(Ah + (size_t)(m0 + lr) * D_MODEL + k0 + lc * 8);
            } else {
                fa0 = *(const float4*)(Af + (size_t)(m0 + lr) * D_MODEL + k0 + lc * 8);
                fa1 = *(const float4*)(Af + (size_t)(m0 + lr) * D_MODEL + k0 + lc * 8 + 4);
            }
            fb0 = *(const float4*)(W + (size_t)(n0 + lr) * D_MODEL + k0 + lc * 8);
            fb1 = *(const float4*)(W + (size_t)(n0 + lr) * D_MODEL + k0 + lc * 8 + 4);
        }

        const uint32_t stA = (uint32_t)(cur * 2 * TILE_W);
        const uint32_t stB = stA + TILE_W;
        {
            uint32_t af[4][4], bf[4][2];
#pragma unroll
            for (int mi = 0; mi < 4; mi++)
                ldsm_x4(af[mi], smem_b + ((stA + (uint32_t)((warp_m * 64 + mi * 16 + a_row) * RSTW + a_coff)) << 2));
#pragma unroll
            for (int ni = 0; ni < 4; ni++)
                ldsm_x2(bf[ni], smem_b + ((stB + (uint32_t)((warp_n * 32 + ni * 8 + b_row) * RSTW + b_coff)) << 2));
#pragma unroll
            for (int mi = 0; mi < 4; mi++)
#pragma unroll
                for (int ni = 0; ni < 4; ni++)
                    mma_f16_16x8x16(acc[mi][ni], af[mi], bf[ni]);
        }

        if (c + 1 < NCHUNK) {
            uint32_t* nb = dsm + (cur ^ 1) * 2 * TILE_W;
            uint4 ua, ub;
            if (AHALF) ua = ha;
            else { ua.x = pack_h2(fa0.x, fa0.y); ua.y = pack_h2(fa0.z, fa0.w);
                   ua.z = pack_h2(fa1.x, fa1.y); ua.w = pack_h2(fa1.z, fa1.w); }
            ub.x = pack_h2(fb0.x, fb0.y); ub.y = pack_h2(fb0.z, fb0.w);
            ub.z = pack_h2(fb1.x, fb1.y); ub.w = pack_h2(fb1.z, fb1.w);
            *(uint4*)(nb + lr * RSTW + lc * 4) = ua;
            *(uint4*)(nb + TILE_W + lr * RSTW + lc * 4) = ub;
        }
        __syncthreads();
        cur ^= 1;
    }

    // ---- epilogue ----
#pragma unroll
    for (int mi = 0; mi < 4; mi++) {
#pragma unroll
        for (int rr = 0; rr < 2; rr++) {
            const int m = m0 + warp_m * 64 + mi * 16 + g + rr * 8;
            const int bb = m >> 11;
            const int l  = m & (SEQ - 1);
#pragma unroll
            for (int ni = 0; ni < 4; ni++) {
                const int n = n0 + warp_n * 32 + ni * 8 + 2 * tig;
                const float v0 = acc[mi][ni][rr * 2 + 0] + bias[n];
                const float v1 = acc[mi][ni][rr * 2 + 1] + bias[n + 1];
                if (HEAD) {
                    const int h  = n >> 6;
                    const int dk = n & (D_K - 1);
                    __half2 hv = __floats2half2_rn(v0, v1);
                    *(__half2*)((__half*)Cp + ((size_t)(bb * N_HEADS + h) * SEQ + l) * D_K + dk) = hv;
                } else {
                    float* Cf = (float*)Cp;
                    Cf[(size_t)m * D_MODEL + n]     = v0;
                    Cf[(size_t)m * D_MODEL + n + 1] = v1;
                }
            }
        }
    }
}

__global__ void __launch_bounds__(256, 2) proj_kernel(
    const float* __restrict__ Q,  const float* __restrict__ K,  const float* __restrict__ V,
    const float* __restrict__ Wq, const float* __restrict__ Wk, const float* __restrict__ Wv,
    const float* __restrict__ bq, const float* __restrict__ bk, const float* __restrict__ bv)
{
    const int z = blockIdx.z;
    if (z == 0)      tc_gemm<false, true>(Q, Wq, bq, g_qh);
    else if (z == 1) tc_gemm<false, true>(K, Wk, bk, g_kh);
    else             tc_gemm<false, true>(V, Wv, bv, g_vh);
}

__global__ void __launch_bounds__(256, 2) out_kernel(
    const float* __restrict__ Wo, const float* __restrict__ bo, float* __restrict__ out)
{
    tc_gemm<true, false>(g_att, Wo, bo, out);
}

// ---------------- f16 tensor-core flash attention ----------------
// CTA: 128 q-rows of one (b,h); kv tiles of 128; online softmax; V via ldmatrix.trans.
__global__ void __launch_bounds__(256) attn_kernel()
{
    extern __shared__ uint32_t dsm[];
    const uint32_t smem_b = (uint32_t)__cvta_generic_to_shared(dsm);
    __half* ph  = (__half*)dsm;              // half-indexed view
    float* m_s  = (float*)(dsm + A_MS);
    float* l_s  = (float*)(dsm + A_LS);
    float* cf_s = (float*)(dsm + A_CF);

    const int tid = threadIdx.x;
    const int wid = tid >> 5;
    const int lid = tid & 31;
    const int g   = lid >> 2;
    const int tig = lid & 3;
    const int warp_m = wid >> 2;          // S phase: 2m x 4n
    const int warp_n = wid & 3;
    const int pwarp_m = wid >> 1;         // PV phase: 4m x 2n
    const int pwarp_n = wid & 1;

    const int a_row  = lid & 15;
    const int a_coff = (lid >> 4) * 4;
    const int b_row  = lid & 7;
    const int b_coff = ((lid >> 3) & 1) * 4;
    const int t_row  = lid & 15;          // trans ldmatrix: 16 consecutive kv rows

    const int bh = blockIdx.y;
    const int q0 = (gridDim.x - 1 - blockIdx.x) * 128;   // heavy blocks first
    const int bb = bh >> 4;
    const int h  = bh & 15;

    // ---- load Q tile (128 rows x 64 halves) ----
    const __half* qb = g_qh + ((size_t)bh * SEQ + q0) * D_K;
#pragma unroll
    for (int it = 0; it < 4; it++) {
        const int s = tid + it * 256;     // 1024 slots = 128 rows x 8 uint4
        const int r = s >> 3, c8 = s & 7;
        const uint4 u = *(const uint4*)(qb + (size_t)r * D_K + c8 * 8);
        *(uint4*)(dsm + A_QS + r * QST + c8 * 4) = u;
    }
    if (tid < 128) { m_s[tid] = -1e30f; l_s[tid] = 0.f; }

    float oacc[2][4][4];
#pragma unroll
    for (int mi = 0; mi < 2; mi++)
#pragma unroll
        for (int ni = 0; ni < 4; ni++)
#pragma unroll
            for (int r = 0; r < 4; r++) oacc[mi][ni][r] = 0.f;

    const int ntiles = q0 / 128 + 1;
    for (int t = 0; t < ntiles; t++) {
        const int kv0 = t * 128;
        __syncthreads();

        // ---- load K and V tiles (each 128 rows x 64 halves, same layout) ----
        const __half* kb = g_kh + ((size_t)bh * SEQ + kv0) * D_K;
        const __half* vb = g_vh + ((size_t)bh * SEQ + kv0) * D_K;
#pragma unroll
        for (int it = 0; it < 4; it++) {
            const int s = tid + it * 256;
            const int r = s >> 3, c8 = s & 7;
            *(uint4*)(dsm + A_KS + r * QST + c8 * 4) = *(const uint4*)(kb + (size_t)r * D_K + c8 * 8);
            *(uint4*)(dsm + A_VS + r * QST + c8 * 4) = *(const uint4*)(vb + (size_t)r * D_K + c8 * 8);
        }
        __syncthreads();

        // ---- S = Q K^T : M=128 N=128 K=64 (4 k16 steps), warps 2m x 4n ----
        {
            float sacc[4][4][4];
#pragma unroll
            for (int mi = 0; mi < 4; mi++)
#pragma unroll
                for (int ni = 0; ni < 4; ni++)
#pragma unroll
                    for (int r = 0; r < 4; r++) sacc[mi][ni][r] = 0.f;

#pragma unroll
            for (int ks = 0; ks < 4; ks++) {
                uint32_t af[4][4], bf[4][2];
#pragma unroll
                for (int mi = 0; mi < 4; mi++)
                    ldsm_x4(af[mi], smem_b + ((uint32_t)(A_QS + (warp_m * 64 + mi * 16 + a_row) * QST + ks * 8 + a_coff) << 2));
#pragma unroll
                for (int ni = 0; ni < 4; ni++)
                    ldsm_x2(bf[ni], smem_b + ((uint32_t)(A_KS + (warp_n * 32 + ni * 8 + b_row) * QST + ks * 8 + b_coff) << 2));
#pragma unroll
                for (int mi = 0; mi < 4; mi++)
#pragma unroll
                    for (int ni = 0; ni < 4; ni++)
                        mma_f16_16x8x16(sacc[mi][ni], af[mi], bf[ni]);
            }

            // scale + causal mask -> S fp32
            const bool diag = (kv0 == q0);
#pragma unroll
            for (int mi = 0; mi < 4; mi++)
#pragma unroll
                for (int rr = 0; rr < 2; rr++) {
                    const int r = warp_m * 64 + mi * 16 + g + rr * 8;
#pragma unroll
                    for (int ni = 0; ni < 4; ni++)
#pragma unroll
                        for (int cc = 0; cc < 2; cc++) {
                            const int ccol = warp_n * 32 + ni * 8 + 2 * tig + cc;
                            float v = sacc[mi][ni][rr * 2 + cc] * 0.125f;
                            if (diag && ccol > r) v = -1e30f;
                            dsm[A_SS + r * SST + ccol] = __float_as_uint(v);
                        }
                }
        }
        __syncthreads();

        // ---- row softmax (2 threads per row), P -> f16 ----
        {
            const int srow = tid >> 1;
            const int half = tid & 1;
            const uint32_t* srcr = dsm + A_SS + srow * SST + half * 64;
            __half* prow = ph + 2 * A_PH + srow * (2 * PSTW) + half * 64;
            float mx = -1e30f;
#pragma unroll 8
            for (int c = 0; c < 64; c++) mx = fmaxf(mx, __uint_as_float(srcr[c]));
            mx = fmaxf(mx, __shfl_xor_sync(0xFFFFFFFFu, mx, 1));
            const float mo = m_s[srow];
            const float mxn = fmaxf(mo, mx);
            float sum = 0.f;
#pragma unroll 8
            for (int c = 0; c < 64; c += 2) {
                const float p0 = __expf(__uint_as_float(srcr[c])     - mxn);
                const float p1 = __expf(__uint_as_float(srcr[c + 1]) - mxn);
                sum += p0 + p1;
                *(__half2*)(prow + c) = __floats2half2_rn(p0, p1);
            }
            sum += __shfl_xor_sync(0xFFFFFFFFu, sum, 1);
            if (half == 0) {
                const float cf = __expf(mo - mxn);
                l_s[srow] = l_s[srow] * cf + sum;
                m_s[srow] = mxn;
                cf_s[srow] = cf;
            }
        }
        __syncthreads();

        // ---- O = O*cf + P @ V : M=128 N=64 K=128 (8 k16 steps), warps 4m x 2n ----
#pragma unroll
        for (int mi = 0; mi < 2; mi++)
#pragma unroll
            for (int rr = 0; rr < 2; rr++) {
                const float cf = cf_s[pwarp_m * 32 + mi * 16 + rr * 8 + g];
#pragma unroll
                for (int ni = 0; ni < 4; ni++)
#pragma unroll
                    for (int cc = 0; cc < 2; cc++)
                        oacc[mi][ni][rr * 2 + cc] *= cf;
            }
#pragma unroll
        for (int ks = 0; ks < 8; ks++) {
            uint32_t af[2][4], bf[4][2];
#pragma unroll
            for (int mi = 0; mi < 2; mi++)
                ldsm_x4(af[mi], smem_b + ((uint32_t)(A_PH + (pwarp_m * 32 + mi * 16 + a_row) * PSTW + ks * 8 + a_coff) << 2));
#pragma unroll
            for (int ni = 0; ni < 4; ni++)
                ldsm_x2_trans(bf[ni], smem_b + ((uint32_t)(A_VS + (ks * 16 + t_row) * QST + pwarp_n * 16 + ni * 4) << 2));
#pragma unroll
            for (int mi = 0; mi < 2; mi++)
#pragma unroll
                for (int ni = 0; ni < 4; ni++)
                    mma_f16_16x8x16(oacc[mi][ni], af[mi], bf[ni]);
        }
    }

    // ---- epilogue: normalize, write g_att halves [B,L,D] ----
#pragma unroll
    for (int mi = 0; mi < 2; mi++)
#pragma unroll
        for (int rr = 0; rr < 2; rr++) {
            const int r = pwarp_m * 32 + mi * 16 + rr * 8 + g;
            const float inv = 1.f / l_s[r];
            const int q = q0 + r;
#pragma unroll
            for (int ni = 0; ni < 4; ni++) {
                const int d = pwarp_n * 32 + ni * 8 + 2 * tig;
                __half2 hv = __floats2half2_rn(oacc[mi][ni][rr * 2 + 0] * inv,
                                               oacc[mi][ni][rr * 2 + 1] * inv);
                *(__half2*)(g_att + ((size_t)bb * SEQ + q) * D_MODEL + h * D_K + d) = hv;
            }
        }
}

// ---------------- launch ----------------
extern "C" void kernel_launch(void* const* d_in, const int* in_sizes, int n_in,
                              void* d_out, int out_size)
{
    const float* Q = (const float*)d_in[0];
    const float* K = (const float*)d_in[1];
    const float* V = (const float*)d_in[2];
    const int wb = (n_in > 3 && in_sizes[3] == SEQ * SEQ) ? 4 : 3;
    const float* Wq = (const float*)d_in[wb + 0];
    const float* bq = (const float*)d_in[wb + 1];
    const float* Wk = (const float*)d_in[wb + 2];
    const float* bk = (const float*)d_in[wb + 3];
    const float* Wv = (const float*)d_in[wb + 4];
    const float* bv = (const float*)d_in[wb + 5];
    const float* Wo = (const float*)d_in[wb + 6];
    const float* bo = (const float*)d_in[wb + 7];
    float* out = (float*)d_out;

    cudaFuncSetAttribute(proj_kernel, cudaFuncAttributeMaxDynamicSharedMemorySize, DSMEM_BYTES);
    cudaFuncSetAttribute(out_kernel,  cudaFuncAttributeMaxDynamicSharedMemorySize, DSMEM_BYTES);
    cudaFuncSetAttribute(attn_kernel, cudaFuncAttributeMaxDynamicSharedMemorySize, ATTN_SMEM_BYTES);

    dim3 blk(256);
    proj_kernel<<<dim3(D_MODEL / 128, M_TOTAL / 128, 3), blk, DSMEM_BYTES>>>(
        Q, K, V, Wq, Wk, Wv, bq, bk, bv);
    attn_kernel<<<dim3(SEQ / 128, BATCH * N_HEADS), blk, ATTN_SMEM_BYTES>>>();
    out_kernel<<<dim3(D_MODEL / 128, M_TOTAL / 128), blk, DSMEM_BYTES>>>(Wo, bo, out);
}